// round 16
// baseline (speedup 1.0000x reference)
#include <cuda_runtime.h>
#include <cuda_bf16.h>
#include <cuda_fp16.h>
#include <math.h>
#include <stdint.h>

#define NN 50000
#define EE 800000
#define HH 128
#define CC 10
#define GG 128
#define NBLK 196   // ceil(NN/256)

// ---------------- device scratch (static, no allocation) ----------------
__device__ int   g_outdeg[NN];
__device__ int   g_indeg[NN];
__device__ float g_csrc[NN];
__device__ float g_cdst[NN];
__device__ int   g_rowptr[NN + 1];
__device__ int   g_fill[NN];
__device__ int   g_col[EE];
__device__ uint2 g_mh[NN * HH / 4];     // y in fp16 (half4 per uint2)
__device__ float g_h1[NN * HH];
__device__ float g_h2[NN * HH];
__device__ float g_hg[GG * HH];
__device__ int   g_part[NBLK];
// W^T split into fp16 hi/lo (lo scaled by 2^11), 4 layers, layout [n][k]
__device__ __half g_wthi[4 * HH * HH];
__device__ __half g_wtlo[4 * HH * HH];

// ---------------- preprocessing ----------------

__global__ void zero_kernel() {
    int i = blockIdx.x * blockDim.x + threadIdx.x;
    if (i < NN) { g_outdeg[i] = 0; g_indeg[i] = 0; }
    if (i == 0) g_rowptr[NN] = EE;
}

// 4 blocks: transpose + fp16-split W for layer b (runs on side stream)
// Whi = fp16(w); Wlo = fp16((w - Whi) * 2048)  [scaled to avoid denormals]
__global__ void wprep_kernel(const float* __restrict__ W0,
                             const float* __restrict__ Ws) {
    const int b = blockIdx.x;
    const int t = threadIdx.x;
    extern __shared__ float s[];   // [128][129] staging
    const float* src = (b == 0) ? W0 : (Ws + (b - 1) * HH * HH);
    for (int i = t; i < 128 * 32; i += 256) {
        int k = i >> 5, q = i & 31;
        float4 v = ((const float4*)src)[i];
        float* d = s + k * 129 + q * 4;
        d[0] = v.x; d[1] = v.y; d[2] = v.z; d[3] = v.w;
    }
    __syncthreads();
    for (int i = t; i < 128 * 32; i += 256) {
        int n = i >> 5, kq = i & 31;
        uint32_t hi2[2], lo2[2];
        #pragma unroll
        for (int h = 0; h < 2; h++) {
            float w0 = s[(kq * 4 + 2 * h + 0) * 129 + n];
            float w1 = s[(kq * 4 + 2 * h + 1) * 129 + n];
            __half h0 = __float2half_rn(w0), h1 = __float2half_rn(w1);
            __half l0 = __float2half_rn((w0 - __half2float(h0)) * 2048.0f);
            __half l1 = __float2half_rn((w1 - __half2float(h1)) * 2048.0f);
            hi2[h] = ((uint32_t)__half_as_ushort(h1) << 16) | __half_as_ushort(h0);
            lo2[h] = ((uint32_t)__half_as_ushort(l1) << 16) | __half_as_ushort(l0);
        }
        ((uint2*)g_wthi)[b * 4096 + i] = make_uint2(hi2[0], hi2[1]);
        ((uint2*)g_wtlo)[b * 4096 + i] = make_uint2(lo2[0], lo2[1]);
    }
}

__global__ void degree_kernel(const int* __restrict__ ei) {
    int e = blockIdx.x * blockDim.x + threadIdx.x;
    if (e >= EE) return;
    atomicAdd(&g_outdeg[ei[e]], 1);
    atomicAdd(&g_indeg[ei[EE + e]], 1);
}

__global__ void scan_p1() {
    int t = threadIdx.x;
    int i = blockIdx.x * 256 + t;
    int v = 0;
    if (i < NN) {
        v = g_indeg[i];
        g_csrc[i] = rsqrtf(fmaxf((float)g_outdeg[i], 1.0f));
        g_cdst[i] = rsqrtf(fmaxf((float)v, 1.0f));
    }
    int lane = t & 31, w = t >> 5;
    int x = v;
    #pragma unroll
    for (int o = 16; o > 0; o >>= 1) x += __shfl_down_sync(~0u, x, o);
    __shared__ int ws[8];
    if (lane == 0) ws[w] = x;
    __syncthreads();
    if (t == 0) {
        int s = 0;
        #pragma unroll
        for (int j = 0; j < 8; j++) s += ws[j];
        g_part[blockIdx.x] = s;
    }
}

__global__ void scan_p3() {
    __shared__ int rs[8];
    __shared__ int ss[8];
    __shared__ int s_off;
    const int t = threadIdx.x, bid = blockIdx.x;
    const int lane = t & 31, w = t >> 5;

    int p = 0;
    for (int j = t; j < bid; j += 256) p += g_part[j];
    int pr = p;
    #pragma unroll
    for (int o = 16; o > 0; o >>= 1) pr += __shfl_down_sync(~0u, pr, o);
    if (lane == 0) rs[w] = pr;
    __syncthreads();
    if (t == 0) {
        int s = 0;
        #pragma unroll
        for (int j = 0; j < 8; j++) s += rs[j];
        s_off = s;
    }
    __syncthreads();
    const int off = s_off;

    int i = bid * 256 + t;
    int v = (i < NN) ? g_indeg[i] : 0;
    int x = v;
    #pragma unroll
    for (int o = 1; o < 32; o <<= 1) {
        int y = __shfl_up_sync(~0u, x, o);
        if (lane >= o) x += y;
    }
    if (lane == 31) ss[w] = x;
    __syncthreads();
    if (t < 8) {
        int s = ss[t];
        #pragma unroll
        for (int o = 1; o < 8; o <<= 1) {
            int y = __shfl_up_sync(0xff, s, o);
            if (t >= o) s += y;
        }
        ss[t] = s;
    }
    __syncthreads();
    int excl = x - v + (w > 0 ? ss[w - 1] : 0) + off;
    if (i < NN) { g_rowptr[i] = excl; g_fill[i] = excl; }
}

__global__ void csr_fill_kernel(const int* __restrict__ ei) {
    int e = blockIdx.x * blockDim.x + threadIdx.x;
    if (e >= EE) return;
    int d = ei[EE + e];
    int pos = atomicAdd(&g_fill[d], 1);
    g_col[pos] = ei[e];
}

// =====================================================================
// GEMM: y = (c_src ⊙ A) @ W via 2-term fp16 split HMMA (m16n8k16 f16)
//   y = A16·Whi + (A16·Wlo') * 2^-11   (Wlo' = Wlo * 2^11, separate accs)
// 128x128 tile, 256 threads = 8 warps (4m x 2n), warp tile 32x64.
// smem 104.4KB -> 2 blocks/SM.
// =====================================================================
#define PITCHB 272                 // 136 fp16 * 2 bytes
#define S_A    0
#define S_BHI  34816
#define S_BLO  69632
#define TC_SMEM 104448

__device__ __forceinline__ uint32_t smem_u32(const void* p) {
    uint32_t a;
    asm("{ .reg .u64 t; cvta.to.shared.u64 t, %1; cvt.u32.u64 %0, t; }"
        : "=r"(a) : "l"(p));
    return a;
}
__device__ __forceinline__ uint32_t lds32(uint32_t a) {
    uint32_t v;
    asm volatile("ld.shared.b32 %0, [%1];" : "=r"(v) : "r"(a));
    return v;
}
__device__ __forceinline__ void mma16816h(float* c, uint32_t a0, uint32_t a1,
                                          uint32_t a2, uint32_t a3,
                                          uint32_t b0, uint32_t b1) {
    asm volatile(
        "mma.sync.aligned.m16n8k16.row.col.f32.f16.f16.f32 "
        "{%0,%1,%2,%3}, {%4,%5,%6,%7}, {%8,%9}, {%0,%1,%2,%3};"
        : "+f"(c[0]), "+f"(c[1]), "+f"(c[2]), "+f"(c[3])
        : "r"(a0), "r"(a1), "r"(a2), "r"(a3), "r"(b0), "r"(b1));
}

__global__ __launch_bounds__(256, 2) void gemm_tc_kernel(
    const float* __restrict__ A,
    const __half* __restrict__ WThi,
    const __half* __restrict__ WTlo,
    __half* __restrict__ out) {
    extern __shared__ char smem[];
    const uint32_t sb = smem_u32(smem);
    const int t = threadIdx.x;
    const int wid = t >> 5, lane = t & 31;
    const int g = lane >> 2, tg = lane & 3;   // group / thread-in-group
    const int wm = wid & 3, wn = wid >> 2;    // warp grid 4m x 2n
    const int row0 = blockIdx.x * 128;

    // ---- load + convert A tile (fp32, scaled by c_src) -> fp16 smem ----
    const float4* A4 = (const float4*)A;
    #pragma unroll
    for (int i = t; i < 128 * 32; i += 256) {
        int r = i >> 5, q = i & 31;
        float4 v = make_float4(0.f, 0.f, 0.f, 0.f);
        float cs = 0.f;
        if (row0 + r < NN) { v = A4[(row0 + r) * 32 + q]; cs = g_csrc[row0 + r]; }
        __half2 p0 = __floats2half2_rn(v.x * cs, v.y * cs);
        __half2 p1 = __floats2half2_rn(v.z * cs, v.w * cs);
        uint32_t off = (uint32_t)(r * PITCHB + q * 8);
        *(uint2*)(smem + S_A + off) =
            make_uint2(*(uint32_t*)&p0, *(uint32_t*)&p1);
    }

    // ---- load prepped WT (fp16 hi / scaled lo) ----
    #pragma unroll
    for (int i = t; i < 128 * 16; i += 256) {
        int n = i >> 4, kq = i & 15;
        uint32_t off = (uint32_t)(n * PITCHB + kq * 16);
        *(uint4*)(smem + S_BHI + off) = ((const uint4*)WThi)[i];
        *(uint4*)(smem + S_BLO + off) = ((const uint4*)WTlo)[i];
    }
    __syncthreads();

    float accH[2][8][4], accL[2][8][4];
    #pragma unroll
    for (int mt = 0; mt < 2; mt++)
        #pragma unroll
        for (int nt = 0; nt < 8; nt++)
            #pragma unroll
            for (int j = 0; j < 4; j++) { accH[mt][nt][j] = 0.f; accL[mt][nt][j] = 0.f; }

    const uint32_t awoff = (uint32_t)((wm * 32 + g) * PITCHB + tg * 4);
    const uint32_t bwoff = (uint32_t)((wn * 64 + g) * PITCHB + tg * 4);
    const uint32_t sA  = sb + S_A + awoff;
    const uint32_t sBh = sb + S_BHI + bwoff;
    const uint32_t sBl = sb + S_BLO + bwoff;

    #pragma unroll
    for (int ks = 0; ks < 8; ks++) {
        const uint32_t koff = (uint32_t)(ks * 32);
        uint32_t ah[2][4];
        #pragma unroll
        for (int mt = 0; mt < 2; mt++) {
            uint32_t aa = sA + mt * (16 * PITCHB) + koff;
            ah[mt][0] = lds32(aa);
            ah[mt][1] = lds32(aa + 8 * PITCHB);
            ah[mt][2] = lds32(aa + 16);
            ah[mt][3] = lds32(aa + 8 * PITCHB + 16);
        }
        #pragma unroll
        for (int nt = 0; nt < 8; nt++) {
            uint32_t bah = sBh + nt * (8 * PITCHB) + koff;
            uint32_t bh0 = lds32(bah), bh1 = lds32(bah + 16);
            uint32_t bal = sBl + nt * (8 * PITCHB) + koff;
            uint32_t bl0 = lds32(bal), bl1 = lds32(bal + 16);
            #pragma unroll
            for (int mt = 0; mt < 2; mt++) {
                mma16816h(accH[mt][nt], ah[mt][0], ah[mt][1], ah[mt][2], ah[mt][3], bh0, bh1);
                mma16816h(accL[mt][nt], ah[mt][0], ah[mt][1], ah[mt][2], ah[mt][3], bl0, bl1);
            }
        }
    }

    // ---- epilogue: combine (hi + lo*2^-11), convert to fp16, store ----
    const float INV2048 = 1.0f / 2048.0f;
    #pragma unroll
    for (int mt = 0; mt < 2; mt++) {
        int ra = row0 + wm * 32 + mt * 16 + g;
        int rb = ra + 8;
        #pragma unroll
        for (int nt = 0; nt < 8; nt++) {
            int col = wn * 64 + nt * 8 + tg * 2;
            float v0 = fmaf(accL[mt][nt][0], INV2048, accH[mt][nt][0]);
            float v1 = fmaf(accL[mt][nt][1], INV2048, accH[mt][nt][1]);
            float v2 = fmaf(accL[mt][nt][2], INV2048, accH[mt][nt][2]);
            float v3 = fmaf(accL[mt][nt][3], INV2048, accH[mt][nt][3]);
            if (ra < NN)
                *(__half2*)(out + ra * HH + col) = __floats2half2_rn(v0, v1);
            if (rb < NN)
                *(__half2*)(out + rb * HH + col) = __floats2half2_rn(v2, v3);
        }
    }
}

// ------- SpMM: h = relu(c_dst ⊙ (A y) + b), fp16 gather, 8-way unroll ------
__global__ void spmm_bias_relu_kernel(const uint2* __restrict__ y,
                                      const float* __restrict__ bias,
                                      float* __restrict__ h) {
    int gw = (blockIdx.x * blockDim.x + threadIdx.x) >> 5;
    int lane = threadIdx.x & 31;
    if (gw >= NN) return;
    int e0 = g_rowptr[gw];
    int e1 = g_rowptr[gw + 1];
    float4 a0 = make_float4(0.f, 0.f, 0.f, 0.f);
    float4 a1 = a0, a2 = a0, a3 = a0;
    int e = e0;
    for (; e + 8 <= e1; e += 8) {
        int s0 = g_col[e],     s1 = g_col[e + 1], s2 = g_col[e + 2], s3 = g_col[e + 3];
        int s4 = g_col[e + 4], s5 = g_col[e + 5], s6 = g_col[e + 6], s7 = g_col[e + 7];
        uint2 u0 = y[s0 * 32 + lane];
        uint2 u1 = y[s1 * 32 + lane];
        uint2 u2 = y[s2 * 32 + lane];
        uint2 u3 = y[s3 * 32 + lane];
        uint2 u4 = y[s4 * 32 + lane];
        uint2 u5 = y[s5 * 32 + lane];
        uint2 u6 = y[s6 * 32 + lane];
        uint2 u7 = y[s7 * 32 + lane];
        float2 p, q;
        p = __half22float2(*(__half2*)&u0.x); q = __half22float2(*(__half2*)&u0.y);
        a0.x += p.x; a0.y += p.y; a0.z += q.x; a0.w += q.y;
        p = __half22float2(*(__half2*)&u1.x); q = __half22float2(*(__half2*)&u1.y);
        a1.x += p.x; a1.y += p.y; a1.z += q.x; a1.w += q.y;
        p = __half22float2(*(__half2*)&u2.x); q = __half22float2(*(__half2*)&u2.y);
        a2.x += p.x; a2.y += p.y; a2.z += q.x; a2.w += q.y;
        p = __half22float2(*(__half2*)&u3.x); q = __half22float2(*(__half2*)&u3.y);
        a3.x += p.x; a3.y += p.y; a3.z += q.x; a3.w += q.y;
        p = __half22float2(*(__half2*)&u4.x); q = __half22float2(*(__half2*)&u4.y);
        a0.x += p.x; a0.y += p.y; a0.z += q.x; a0.w += q.y;
        p = __half22float2(*(__half2*)&u5.x); q = __half22float2(*(__half2*)&u5.y);
        a1.x += p.x; a1.y += p.y; a1.z += q.x; a1.w += q.y;
        p = __half22float2(*(__half2*)&u6.x); q = __half22float2(*(__half2*)&u6.y);
        a2.x += p.x; a2.y += p.y; a2.z += q.x; a2.w += q.y;
        p = __half22float2(*(__half2*)&u7.x); q = __half22float2(*(__half2*)&u7.y);
        a3.x += p.x; a3.y += p.y; a3.z += q.x; a3.w += q.y;
    }
    for (; e + 4 <= e1; e += 4) {
        int s0 = g_col[e], s1 = g_col[e + 1], s2 = g_col[e + 2], s3 = g_col[e + 3];
        uint2 u0 = y[s0 * 32 + lane];
        uint2 u1 = y[s1 * 32 + lane];
        uint2 u2 = y[s2 * 32 + lane];
        uint2 u3 = y[s3 * 32 + lane];
        float2 p, q;
        p = __half22float2(*(__half2*)&u0.x); q = __half22float2(*(__half2*)&u0.y);
        a0.x += p.x; a0.y += p.y; a0.z += q.x; a0.w += q.y;
        p = __half22float2(*(__half2*)&u1.x); q = __half22float2(*(__half2*)&u1.y);
        a1.x += p.x; a1.y += p.y; a1.z += q.x; a1.w += q.y;
        p = __half22float2(*(__half2*)&u2.x); q = __half22float2(*(__half2*)&u2.y);
        a2.x += p.x; a2.y += p.y; a2.z += q.x; a2.w += q.y;
        p = __half22float2(*(__half2*)&u3.x); q = __half22float2(*(__half2*)&u3.y);
        a3.x += p.x; a3.y += p.y; a3.z += q.x; a3.w += q.y;
    }
    for (; e < e1; e++) {
        int s = g_col[e];
        uint2 u = y[s * 32 + lane];
        float2 p = __half22float2(*(__half2*)&u.x);
        float2 q = __half22float2(*(__half2*)&u.y);
        a0.x += p.x; a0.y += p.y; a0.z += q.x; a0.w += q.y;
    }
    float cd = g_cdst[gw];
    float4 bv = ((const float4*)bias)[lane];
    float4 o;
    o.x = fmaxf((a0.x + a1.x + a2.x + a3.x) * cd + bv.x, 0.f);
    o.y = fmaxf((a0.y + a1.y + a2.y + a3.y) * cd + bv.y, 0.f);
    o.z = fmaxf((a0.z + a1.z + a2.z + a3.z) * cd + bv.z, 0.f);
    o.w = fmaxf((a0.w + a1.w + a2.w + a3.w) * cd + bv.w, 0.f);
    ((float4*)h)[gw * 32 + lane] = o;
}

// ---------------- readout + head ----------------
__global__ void readout_kernel(const float* __restrict__ h, const int* __restrict__ gid) {
    int g = blockIdx.x;
    int f = threadIdx.x;
    int lo = 0, hi = NN;
    while (lo < hi) { int mid = (lo + hi) >> 1; if (gid[mid] < g) lo = mid + 1; else hi = mid; }
    int start = lo;
    lo = start; hi = NN;
    while (lo < hi) { int mid = (lo + hi) >> 1; if (gid[mid] < g + 1) lo = mid + 1; else hi = mid; }
    int end = lo;

    float s = 0.f;
    for (int n = start; n < end; n++) s += h[n * HH + f];
    float cnt = (float)(end - start);
    g_hg[g * HH + f] = s / fmaxf(cnt, 1.0f);
}

__global__ void final_kernel(const float* __restrict__ Wc, const float* __restrict__ bc,
                             float* __restrict__ out) {
    int idx = blockIdx.x * blockDim.x + threadIdx.x;
    if (idx >= GG * CC) return;
    int g = idx / CC, c = idx % CC;
    float sum = 0.f;
    #pragma unroll 8
    for (int k = 0; k < HH; k++) sum = fmaf(g_hg[g * HH + k], Wc[k * CC + c], sum);
    out[idx] = sum + bc[c];
}

// ---------------- host launcher ----------------
extern "C" void kernel_launch(void* const* d_in, const int* in_sizes, int n_in,
                              void* d_out, int out_size) {
    const float* x   = (const float*)d_in[0];
    const float* W0  = (const float*)d_in[1];
    const float* b0  = (const float*)d_in[2];
    const float* Ws  = (const float*)d_in[3];
    const float* bs  = (const float*)d_in[4];
    const float* Wc  = (const float*)d_in[5];
    const float* bc  = (const float*)d_in[6];
    const int*   ei  = (const int*)d_in[7];
    const int*   gid = (const int*)d_in[8];
    float* out = (float*)d_out;

    float *h1, *h2;
    uint2* mh;
    cudaGetSymbolAddress((void**)&h1, g_h1);
    cudaGetSymbolAddress((void**)&h2, g_h2);
    cudaGetSymbolAddress((void**)&mh, g_mh);
    __half *wthi, *wtlo;
    cudaGetSymbolAddress((void**)&wthi, g_wthi);
    cudaGetSymbolAddress((void**)&wtlo, g_wtlo);

    // one-time host resources (no device memory)
    static cudaStream_t s2 = nullptr;
    static cudaEvent_t ev_fork = nullptr, ev_join = nullptr, ev_wprep = nullptr;
    if (s2 == nullptr) {
        cudaStreamCreateWithFlags(&s2, cudaStreamNonBlocking);
        cudaEventCreateWithFlags(&ev_fork, cudaEventDisableTiming);
        cudaEventCreateWithFlags(&ev_join, cudaEventDisableTiming);
        cudaEventCreateWithFlags(&ev_wprep, cudaEventDisableTiming);
    }

    const int WPREP_SMEM = 128 * 129 * 4;   // 66048
    cudaFuncSetAttribute(wprep_kernel,
                         cudaFuncAttributeMaxDynamicSharedMemorySize, WPREP_SMEM);
    cudaFuncSetAttribute(gemm_tc_kernel,
                         cudaFuncAttributeMaxDynamicSharedMemorySize, TC_SMEM);

    const int SPMM_BLOCKS = (NN + 7) / 8;
    const int TC_BLOCKS = (NN + 127) / 128;   // 391

    // ---- s2: W prep runs from t=0 (depends on nothing) ----
    cudaEventRecord(ev_fork, 0);
    cudaStreamWaitEvent(s2, ev_fork, 0);
    wprep_kernel<<<4, 256, WPREP_SMEM, s2>>>(W0, Ws);
    cudaEventRecord(ev_wprep, s2);

    // ---- stream 0: degree chain ----
    zero_kernel<<<NBLK, 256>>>();
    degree_kernel<<<(EE + 255) / 256, 256>>>(ei);
    scan_p1<<<NBLK, 256>>>();

    // fork CSR build (s2, after scan_p1)
    cudaEventRecord(ev_fork, 0);
    cudaStreamWaitEvent(s2, ev_fork, 0);
    scan_p3<<<NBLK, 256, 0, s2>>>();
    csr_fill_kernel<<<(EE + 255) / 256, 256, 0, s2>>>(ei);
    cudaEventRecord(ev_join, s2);

    // layer-0 GEMM on stream 0 (needs scan_p1 done + wprep done)
    cudaStreamWaitEvent(0, ev_wprep, 0);
    gemm_tc_kernel<<<TC_BLOCKS, 256, TC_SMEM>>>(x, wthi, wtlo, (__half*)mh);

    // join before first SpMM (needs CSR)
    cudaStreamWaitEvent(0, ev_join, 0);

    spmm_bias_relu_kernel<<<SPMM_BLOCKS, 256>>>(mh, b0, h1);
    gemm_tc_kernel<<<TC_BLOCKS, 256, TC_SMEM>>>(h1, wthi + 1 * HH * HH, wtlo + 1 * HH * HH, (__half*)mh);
    spmm_bias_relu_kernel<<<SPMM_BLOCKS, 256>>>(mh, bs + 0 * 128, h2);
    gemm_tc_kernel<<<TC_BLOCKS, 256, TC_SMEM>>>(h2, wthi + 2 * HH * HH, wtlo + 2 * HH * HH, (__half*)mh);
    spmm_bias_relu_kernel<<<SPMM_BLOCKS, 256>>>(mh, bs + 1 * 128, h1);
    gemm_tc_kernel<<<TC_BLOCKS, 256, TC_SMEM>>>(h1, wthi + 3 * HH * HH, wtlo + 3 * HH * HH, (__half*)mh);
    spmm_bias_relu_kernel<<<SPMM_BLOCKS, 256>>>(mh, bs + 2 * 128, h2);

    readout_kernel<<<GG, HH>>>(h2, gid);
    final_kernel<<<(GG * CC + 127) / 128, 128>>>(Wc, bc, out);
}

// round 17
// speedup vs baseline: 1.2404x; 1.2404x over previous
#include <cuda_runtime.h>
#include <cuda_bf16.h>
#include <cuda_fp16.h>
#include <math.h>
#include <stdint.h>

#define NN 50000
#define EE 800000
#define HH 128
#define CC 10
#define GG 128
#define NBLK 196   // ceil(NN/256)

// ---------------- device scratch (static, no allocation) ----------------
__device__ int   g_outdeg[NN];
__device__ int   g_indeg[NN];
__device__ float g_csrc[NN];
__device__ float g_cdst[NN];
__device__ int   g_rowptr[NN + 1];
__device__ int   g_fill[NN];
__device__ int   g_col[EE];
__device__ uint2 g_mh[NN * HH / 4];     // y in fp16 (half4 per uint2)
__device__ float g_h1[NN * HH];
__device__ float g_h2[NN * HH];
__device__ float g_hg[GG * HH];
__device__ int   g_part[NBLK];
// W^T split into fp16 hi/lo (lo scaled by 2^11), 4 layers, layout [n][k]
__device__ __half g_wthi[4 * HH * HH];
__device__ __half g_wtlo[4 * HH * HH];

// ---------------- preprocessing ----------------

__global__ void zero_kernel() {
    int i = blockIdx.x * blockDim.x + threadIdx.x;
    if (i < NN) { g_outdeg[i] = 0; g_indeg[i] = 0; }
    if (i == 0) g_rowptr[NN] = EE;
}

// 4 blocks: transpose + fp16-split W for layer b (runs on side stream)
// Whi = fp16(w); Wlo = fp16((w - Whi) * 2048)  [scaled to avoid denormals]
__global__ void wprep_kernel(const float* __restrict__ W0,
                             const float* __restrict__ Ws) {
    const int b = blockIdx.x;
    const int t = threadIdx.x;
    extern __shared__ float s[];   // [128][129] staging
    const float* src = (b == 0) ? W0 : (Ws + (b - 1) * HH * HH);
    for (int i = t; i < 128 * 32; i += 256) {
        int k = i >> 5, q = i & 31;
        float4 v = ((const float4*)src)[i];
        float* d = s + k * 129 + q * 4;
        d[0] = v.x; d[1] = v.y; d[2] = v.z; d[3] = v.w;
    }
    __syncthreads();
    for (int i = t; i < 128 * 32; i += 256) {
        int n = i >> 5, kq = i & 31;
        uint32_t hi2[2], lo2[2];
        #pragma unroll
        for (int h = 0; h < 2; h++) {
            float w0 = s[(kq * 4 + 2 * h + 0) * 129 + n];
            float w1 = s[(kq * 4 + 2 * h + 1) * 129 + n];
            __half h0 = __float2half_rn(w0), h1 = __float2half_rn(w1);
            __half l0 = __float2half_rn((w0 - __half2float(h0)) * 2048.0f);
            __half l1 = __float2half_rn((w1 - __half2float(h1)) * 2048.0f);
            hi2[h] = ((uint32_t)__half_as_ushort(h1) << 16) | __half_as_ushort(h0);
            lo2[h] = ((uint32_t)__half_as_ushort(l1) << 16) | __half_as_ushort(l0);
        }
        ((uint2*)g_wthi)[b * 4096 + i] = make_uint2(hi2[0], hi2[1]);
        ((uint2*)g_wtlo)[b * 4096 + i] = make_uint2(lo2[0], lo2[1]);
    }
}

__global__ void degree_kernel(const int* __restrict__ ei) {
    int e = blockIdx.x * blockDim.x + threadIdx.x;
    if (e >= EE) return;
    atomicAdd(&g_outdeg[ei[e]], 1);
    atomicAdd(&g_indeg[ei[EE + e]], 1);
}

__global__ void scan_p1() {
    int t = threadIdx.x;
    int i = blockIdx.x * 256 + t;
    int v = 0;
    if (i < NN) {
        v = g_indeg[i];
        g_csrc[i] = rsqrtf(fmaxf((float)g_outdeg[i], 1.0f));
        g_cdst[i] = rsqrtf(fmaxf((float)v, 1.0f));
    }
    int lane = t & 31, w = t >> 5;
    int x = v;
    #pragma unroll
    for (int o = 16; o > 0; o >>= 1) x += __shfl_down_sync(~0u, x, o);
    __shared__ int ws[8];
    if (lane == 0) ws[w] = x;
    __syncthreads();
    if (t == 0) {
        int s = 0;
        #pragma unroll
        for (int j = 0; j < 8; j++) s += ws[j];
        g_part[blockIdx.x] = s;
    }
}

__global__ void scan_p3() {
    __shared__ int rs[8];
    __shared__ int ss[8];
    __shared__ int s_off;
    const int t = threadIdx.x, bid = blockIdx.x;
    const int lane = t & 31, w = t >> 5;

    int p = 0;
    for (int j = t; j < bid; j += 256) p += g_part[j];
    int pr = p;
    #pragma unroll
    for (int o = 16; o > 0; o >>= 1) pr += __shfl_down_sync(~0u, pr, o);
    if (lane == 0) rs[w] = pr;
    __syncthreads();
    if (t == 0) {
        int s = 0;
        #pragma unroll
        for (int j = 0; j < 8; j++) s += rs[j];
        s_off = s;
    }
    __syncthreads();
    const int off = s_off;

    int i = bid * 256 + t;
    int v = (i < NN) ? g_indeg[i] : 0;
    int x = v;
    #pragma unroll
    for (int o = 1; o < 32; o <<= 1) {
        int y = __shfl_up_sync(~0u, x, o);
        if (lane >= o) x += y;
    }
    if (lane == 31) ss[w] = x;
    __syncthreads();
    if (t < 8) {
        int s = ss[t];
        #pragma unroll
        for (int o = 1; o < 8; o <<= 1) {
            int y = __shfl_up_sync(0xff, s, o);
            if (t >= o) s += y;
        }
        ss[t] = s;
    }
    __syncthreads();
    int excl = x - v + (w > 0 ? ss[w - 1] : 0) + off;
    if (i < NN) { g_rowptr[i] = excl; g_fill[i] = excl; }
}

__global__ void csr_fill_kernel(const int* __restrict__ ei) {
    int e = blockIdx.x * blockDim.x + threadIdx.x;
    if (e >= EE) return;
    int d = ei[EE + e];
    int pos = atomicAdd(&g_fill[d], 1);
    g_col[pos] = ei[e];
}

// =====================================================================
// GEMM: y = (c_src ⊙ A) @ W via 2-term fp16 split HMMA (m16n8k16 f16)
//   y = A16·Whi + (A16·Wlo') * 2^-11   (Wlo' = Wlo * 2^11, separate accs)
// 128x128 tile, 256 threads = 8 warps (4m x 2n), warp tile 32x64.
// NO min-blocks clause: regs float (~180), no spills, 1 block/SM.
// =====================================================================
#define PITCHB 272                 // 136 fp16 * 2 bytes
#define S_A    0
#define S_BHI  34816
#define S_BLO  69632
#define TC_SMEM 104448

__device__ __forceinline__ uint32_t smem_u32(const void* p) {
    uint32_t a;
    asm("{ .reg .u64 t; cvta.to.shared.u64 t, %1; cvt.u32.u64 %0, t; }"
        : "=r"(a) : "l"(p));
    return a;
}
__device__ __forceinline__ uint32_t lds32(uint32_t a) {
    uint32_t v;
    asm volatile("ld.shared.b32 %0, [%1];" : "=r"(v) : "r"(a));
    return v;
}
__device__ __forceinline__ void mma16816h(float* c, uint32_t a0, uint32_t a1,
                                          uint32_t a2, uint32_t a3,
                                          uint32_t b0, uint32_t b1) {
    asm volatile(
        "mma.sync.aligned.m16n8k16.row.col.f32.f16.f16.f32 "
        "{%0,%1,%2,%3}, {%4,%5,%6,%7}, {%8,%9}, {%0,%1,%2,%3};"
        : "+f"(c[0]), "+f"(c[1]), "+f"(c[2]), "+f"(c[3])
        : "r"(a0), "r"(a1), "r"(a2), "r"(a3), "r"(b0), "r"(b1));
}

__global__ __launch_bounds__(256) void gemm_tc_kernel(
    const float* __restrict__ A,
    const __half* __restrict__ WThi,
    const __half* __restrict__ WTlo,
    __half* __restrict__ out) {
    extern __shared__ char smem[];
    const uint32_t sb = smem_u32(smem);
    const int t = threadIdx.x;
    const int wid = t >> 5, lane = t & 31;
    const int g = lane >> 2, tg = lane & 3;   // group / thread-in-group
    const int wm = wid & 3, wn = wid >> 2;    // warp grid 4m x 2n
    const int row0 = blockIdx.x * 128;

    // ---- load + convert A tile (fp32, scaled by c_src) -> fp16 smem ----
    const float4* A4 = (const float4*)A;
    #pragma unroll
    for (int i = t; i < 128 * 32; i += 256) {
        int r = i >> 5, q = i & 31;
        float4 v = make_float4(0.f, 0.f, 0.f, 0.f);
        float cs = 0.f;
        if (row0 + r < NN) { v = A4[(row0 + r) * 32 + q]; cs = g_csrc[row0 + r]; }
        __half2 p0 = __floats2half2_rn(v.x * cs, v.y * cs);
        __half2 p1 = __floats2half2_rn(v.z * cs, v.w * cs);
        uint32_t off = (uint32_t)(r * PITCHB + q * 8);
        *(uint2*)(smem + S_A + off) =
            make_uint2(*(uint32_t*)&p0, *(uint32_t*)&p1);
    }

    // ---- load prepped WT (fp16 hi / scaled lo) ----
    #pragma unroll
    for (int i = t; i < 128 * 16; i += 256) {
        int n = i >> 4, kq = i & 15;
        uint32_t off = (uint32_t)(n * PITCHB + kq * 16);
        *(uint4*)(smem + S_BHI + off) = ((const uint4*)WThi)[i];
        *(uint4*)(smem + S_BLO + off) = ((const uint4*)WTlo)[i];
    }
    __syncthreads();

    float accH[2][8][4], accL[2][8][4];
    #pragma unroll
    for (int mt = 0; mt < 2; mt++)
        #pragma unroll
        for (int nt = 0; nt < 8; nt++)
            #pragma unroll
            for (int j = 0; j < 4; j++) { accH[mt][nt][j] = 0.f; accL[mt][nt][j] = 0.f; }

    const uint32_t awoff = (uint32_t)((wm * 32 + g) * PITCHB + tg * 4);
    const uint32_t bwoff = (uint32_t)((wn * 64 + g) * PITCHB + tg * 4);
    const uint32_t sA  = sb + S_A + awoff;
    const uint32_t sBh = sb + S_BHI + bwoff;
    const uint32_t sBl = sb + S_BLO + bwoff;

    #pragma unroll
    for (int ks = 0; ks < 8; ks++) {
        const uint32_t koff = (uint32_t)(ks * 32);
        uint32_t ah[2][4];
        #pragma unroll
        for (int mt = 0; mt < 2; mt++) {
            uint32_t aa = sA + mt * (16 * PITCHB) + koff;
            ah[mt][0] = lds32(aa);
            ah[mt][1] = lds32(aa + 8 * PITCHB);
            ah[mt][2] = lds32(aa + 16);
            ah[mt][3] = lds32(aa + 8 * PITCHB + 16);
        }
        #pragma unroll
        for (int nt = 0; nt < 8; nt++) {
            uint32_t bah = sBh + nt * (8 * PITCHB) + koff;
            uint32_t bh0 = lds32(bah), bh1 = lds32(bah + 16);
            uint32_t bal = sBl + nt * (8 * PITCHB) + koff;
            uint32_t bl0 = lds32(bal), bl1 = lds32(bal + 16);
            #pragma unroll
            for (int mt = 0; mt < 2; mt++) {
                mma16816h(accH[mt][nt], ah[mt][0], ah[mt][1], ah[mt][2], ah[mt][3], bh0, bh1);
                mma16816h(accL[mt][nt], ah[mt][0], ah[mt][1], ah[mt][2], ah[mt][3], bl0, bl1);
            }
        }
    }

    // ---- epilogue: combine (hi + lo*2^-11), convert to fp16, store ----
    const float INV2048 = 1.0f / 2048.0f;
    #pragma unroll
    for (int mt = 0; mt < 2; mt++) {
        int ra = row0 + wm * 32 + mt * 16 + g;
        int rb = ra + 8;
        #pragma unroll
        for (int nt = 0; nt < 8; nt++) {
            int col = wn * 64 + nt * 8 + tg * 2;
            float v0 = fmaf(accL[mt][nt][0], INV2048, accH[mt][nt][0]);
            float v1 = fmaf(accL[mt][nt][1], INV2048, accH[mt][nt][1]);
            float v2 = fmaf(accL[mt][nt][2], INV2048, accH[mt][nt][2]);
            float v3 = fmaf(accL[mt][nt][3], INV2048, accH[mt][nt][3]);
            if (ra < NN)
                *(__half2*)(out + ra * HH + col) = __floats2half2_rn(v0, v1);
            if (rb < NN)
                *(__half2*)(out + rb * HH + col) = __floats2half2_rn(v2, v3);
        }
    }
}

// ------- SpMM: h = relu(c_dst ⊙ (A y) + b), fp16 gather, 8-way unroll ------
__global__ void spmm_bias_relu_kernel(const uint2* __restrict__ y,
                                      const float* __restrict__ bias,
                                      float* __restrict__ h) {
    int gw = (blockIdx.x * blockDim.x + threadIdx.x) >> 5;
    int lane = threadIdx.x & 31;
    if (gw >= NN) return;
    int e0 = g_rowptr[gw];
    int e1 = g_rowptr[gw + 1];
    float4 a0 = make_float4(0.f, 0.f, 0.f, 0.f);
    float4 a1 = a0, a2 = a0, a3 = a0;
    int e = e0;
    for (; e + 8 <= e1; e += 8) {
        int s0 = g_col[e],     s1 = g_col[e + 1], s2 = g_col[e + 2], s3 = g_col[e + 3];
        int s4 = g_col[e + 4], s5 = g_col[e + 5], s6 = g_col[e + 6], s7 = g_col[e + 7];
        uint2 u0 = y[s0 * 32 + lane];
        uint2 u1 = y[s1 * 32 + lane];
        uint2 u2 = y[s2 * 32 + lane];
        uint2 u3 = y[s3 * 32 + lane];
        uint2 u4 = y[s4 * 32 + lane];
        uint2 u5 = y[s5 * 32 + lane];
        uint2 u6 = y[s6 * 32 + lane];
        uint2 u7 = y[s7 * 32 + lane];
        float2 p, q;
        p = __half22float2(*(__half2*)&u0.x); q = __half22float2(*(__half2*)&u0.y);
        a0.x += p.x; a0.y += p.y; a0.z += q.x; a0.w += q.y;
        p = __half22float2(*(__half2*)&u1.x); q = __half22float2(*(__half2*)&u1.y);
        a1.x += p.x; a1.y += p.y; a1.z += q.x; a1.w += q.y;
        p = __half22float2(*(__half2*)&u2.x); q = __half22float2(*(__half2*)&u2.y);
        a2.x += p.x; a2.y += p.y; a2.z += q.x; a2.w += q.y;
        p = __half22float2(*(__half2*)&u3.x); q = __half22float2(*(__half2*)&u3.y);
        a3.x += p.x; a3.y += p.y; a3.z += q.x; a3.w += q.y;
        p = __half22float2(*(__half2*)&u4.x); q = __half22float2(*(__half2*)&u4.y);
        a0.x += p.x; a0.y += p.y; a0.z += q.x; a0.w += q.y;
        p = __half22float2(*(__half2*)&u5.x); q = __half22float2(*(__half2*)&u5.y);
        a1.x += p.x; a1.y += p.y; a1.z += q.x; a1.w += q.y;
        p = __half22float2(*(__half2*)&u6.x); q = __half22float2(*(__half2*)&u6.y);
        a2.x += p.x; a2.y += p.y; a2.z += q.x; a2.w += q.y;
        p = __half22float2(*(__half2*)&u7.x); q = __half22float2(*(__half2*)&u7.y);
        a3.x += p.x; a3.y += p.y; a3.z += q.x; a3.w += q.y;
    }
    for (; e + 4 <= e1; e += 4) {
        int s0 = g_col[e], s1 = g_col[e + 1], s2 = g_col[e + 2], s3 = g_col[e + 3];
        uint2 u0 = y[s0 * 32 + lane];
        uint2 u1 = y[s1 * 32 + lane];
        uint2 u2 = y[s2 * 32 + lane];
        uint2 u3 = y[s3 * 32 + lane];
        float2 p, q;
        p = __half22float2(*(__half2*)&u0.x); q = __half22float2(*(__half2*)&u0.y);
        a0.x += p.x; a0.y += p.y; a0.z += q.x; a0.w += q.y;
        p = __half22float2(*(__half2*)&u1.x); q = __half22float2(*(__half2*)&u1.y);
        a1.x += p.x; a1.y += p.y; a1.z += q.x; a1.w += q.y;
        p = __half22float2(*(__half2*)&u2.x); q = __half22float2(*(__half2*)&u2.y);
        a2.x += p.x; a2.y += p.y; a2.z += q.x; a2.w += q.y;
        p = __half22float2(*(__half2*)&u3.x); q = __half22float2(*(__half2*)&u3.y);
        a3.x += p.x; a3.y += p.y; a3.z += q.x; a3.w += q.y;
    }
    for (; e < e1; e++) {
        int s = g_col[e];
        uint2 u = y[s * 32 + lane];
        float2 p = __half22float2(*(__half2*)&u.x);
        float2 q = __half22float2(*(__half2*)&u.y);
        a0.x += p.x; a0.y += p.y; a0.z += q.x; a0.w += q.y;
    }
    float cd = g_cdst[gw];
    float4 bv = ((const float4*)bias)[lane];
    float4 o;
    o.x = fmaxf((a0.x + a1.x + a2.x + a3.x) * cd + bv.x, 0.f);
    o.y = fmaxf((a0.y + a1.y + a2.y + a3.y) * cd + bv.y, 0.f);
    o.z = fmaxf((a0.z + a1.z + a2.z + a3.z) * cd + bv.z, 0.f);
    o.w = fmaxf((a0.w + a1.w + a2.w + a3.w) * cd + bv.w, 0.f);
    ((float4*)h)[gw * 32 + lane] = o;
}

// ---------------- readout + head ----------------
__global__ void readout_kernel(const float* __restrict__ h, const int* __restrict__ gid) {
    int g = blockIdx.x;
    int f = threadIdx.x;
    int lo = 0, hi = NN;
    while (lo < hi) { int mid = (lo + hi) >> 1; if (gid[mid] < g) lo = mid + 1; else hi = mid; }
    int start = lo;
    lo = start; hi = NN;
    while (lo < hi) { int mid = (lo + hi) >> 1; if (gid[mid] < g + 1) lo = mid + 1; else hi = mid; }
    int end = lo;

    float s = 0.f;
    for (int n = start; n < end; n++) s += h[n * HH + f];
    float cnt = (float)(end - start);
    g_hg[g * HH + f] = s / fmaxf(cnt, 1.0f);
}

__global__ void final_kernel(const float* __restrict__ Wc, const float* __restrict__ bc,
                             float* __restrict__ out) {
    int idx = blockIdx.x * blockDim.x + threadIdx.x;
    if (idx >= GG * CC) return;
    int g = idx / CC, c = idx % CC;
    float sum = 0.f;
    #pragma unroll 8
    for (int k = 0; k < HH; k++) sum = fmaf(g_hg[g * HH + k], Wc[k * CC + c], sum);
    out[idx] = sum + bc[c];
}

// ---------------- host launcher ----------------
extern "C" void kernel_launch(void* const* d_in, const int* in_sizes, int n_in,
                              void* d_out, int out_size) {
    const float* x   = (const float*)d_in[0];
    const float* W0  = (const float*)d_in[1];
    const float* b0  = (const float*)d_in[2];
    const float* Ws  = (const float*)d_in[3];
    const float* bs  = (const float*)d_in[4];
    const float* Wc  = (const float*)d_in[5];
    const float* bc  = (const float*)d_in[6];
    const int*   ei  = (const int*)d_in[7];
    const int*   gid = (const int*)d_in[8];
    float* out = (float*)d_out;

    float *h1, *h2;
    uint2* mh;
    cudaGetSymbolAddress((void**)&h1, g_h1);
    cudaGetSymbolAddress((void**)&h2, g_h2);
    cudaGetSymbolAddress((void**)&mh, g_mh);
    __half *wthi, *wtlo;
    cudaGetSymbolAddress((void**)&wthi, g_wthi);
    cudaGetSymbolAddress((void**)&wtlo, g_wtlo);

    // one-time host resources (no device memory)
    static cudaStream_t s2 = nullptr;
    static cudaEvent_t ev_fork = nullptr, ev_join = nullptr, ev_wprep = nullptr;
    if (s2 == nullptr) {
        cudaStreamCreateWithFlags(&s2, cudaStreamNonBlocking);
        cudaEventCreateWithFlags(&ev_fork, cudaEventDisableTiming);
        cudaEventCreateWithFlags(&ev_join, cudaEventDisableTiming);
        cudaEventCreateWithFlags(&ev_wprep, cudaEventDisableTiming);
    }

    const int WPREP_SMEM = 128 * 129 * 4;   // 66048
    cudaFuncSetAttribute(wprep_kernel,
                         cudaFuncAttributeMaxDynamicSharedMemorySize, WPREP_SMEM);
    cudaFuncSetAttribute(gemm_tc_kernel,
                         cudaFuncAttributeMaxDynamicSharedMemorySize, TC_SMEM);

    const int SPMM_BLOCKS = (NN + 7) / 8;
    const int TC_BLOCKS = (NN + 127) / 128;   // 391

    // ---- s2: W prep runs from t=0 (depends on nothing) ----
    cudaEventRecord(ev_fork, 0);
    cudaStreamWaitEvent(s2, ev_fork, 0);
    wprep_kernel<<<4, 256, WPREP_SMEM, s2>>>(W0, Ws);
    cudaEventRecord(ev_wprep, s2);

    // ---- stream 0: degree chain ----
    zero_kernel<<<NBLK, 256>>>();
    degree_kernel<<<(EE + 255) / 256, 256>>>(ei);
    scan_p1<<<NBLK, 256>>>();

    // fork CSR build (s2, after scan_p1)
    cudaEventRecord(ev_fork, 0);
    cudaStreamWaitEvent(s2, ev_fork, 0);
    scan_p3<<<NBLK, 256, 0, s2>>>();
    csr_fill_kernel<<<(EE + 255) / 256, 256, 0, s2>>>(ei);
    cudaEventRecord(ev_join, s2);

    // layer-0 GEMM on stream 0 (needs scan_p1 done + wprep done)
    cudaStreamWaitEvent(0, ev_wprep, 0);
    gemm_tc_kernel<<<TC_BLOCKS, 256, TC_SMEM>>>(x, wthi, wtlo, (__half*)mh);

    // join before first SpMM (needs CSR)
    cudaStreamWaitEvent(0, ev_join, 0);

    spmm_bias_relu_kernel<<<SPMM_BLOCKS, 256>>>(mh, b0, h1);
    gemm_tc_kernel<<<TC_BLOCKS, 256, TC_SMEM>>>(h1, wthi + 1 * HH * HH, wtlo + 1 * HH * HH, (__half*)mh);
    spmm_bias_relu_kernel<<<SPMM_BLOCKS, 256>>>(mh, bs + 0 * 128, h2);
    gemm_tc_kernel<<<TC_BLOCKS, 256, TC_SMEM>>>(h2, wthi + 2 * HH * HH, wtlo + 2 * HH * HH, (__half*)mh);
    spmm_bias_relu_kernel<<<SPMM_BLOCKS, 256>>>(mh, bs + 1 * 128, h1);
    gemm_tc_kernel<<<TC_BLOCKS, 256, TC_SMEM>>>(h1, wthi + 3 * HH * HH, wtlo + 3 * HH * HH, (__half*)mh);
    spmm_bias_relu_kernel<<<SPMM_BLOCKS, 256>>>(mh, bs + 2 * 128, h2);

    readout_kernel<<<GG, HH>>>(h2, gid);
    final_kernel<<<(GG * CC + 127) / 128, 128>>>(Wc, bc, out);
}